// round 2
// baseline (speedup 1.0000x reference)
#include <cuda_runtime.h>
#include <math.h>

#define BATCH   2
#define SEQ     2048
#define DMODEL  1024
#define NHEADS  16
#define DHEAD   64
#define DHALF   32
#define MROWS   (BATCH*SEQ)   // 4096

// ---- scratch (allocation-free: __device__ globals) ----
static __device__ float g_Q[BATCH*NHEADS*SEQ*DHEAD];   // 16 MB
static __device__ float g_K[BATCH*NHEADS*SEQ*DHEAD];   // 16 MB
static __device__ float g_V[BATCH*NHEADS*SEQ*DHEAD];   // 16 MB
static __device__ float g_A[MROWS*DMODEL];             // 16 MB  attention out, [B*S, D]
static __device__ float g_cos[SEQ*DHALF];
static __device__ float g_sin[SEQ*DHALF];

// ============================================================
// RoPE table: angle = pos * theta^(-2i/64), freq in double.
// ============================================================
__global__ void rope_table_kernel(const int* __restrict__ tpos) {
    int idx = blockIdx.x * blockDim.x + threadIdx.x;
    if (idx >= SEQ * DHALF) return;
    int s = idx >> 5;
    int i = idx & 31;
    // ln(10000)/32 = 0.28782313662425572
    double freq = exp(-0.28782313662425572 * (double)i);
    float ang = (float)((double)tpos[s] * freq);
    float sn, cs;
    sincosf(ang, &sn, &cs);
    g_cos[idx] = cs;
    g_sin[idx] = sn;
}

// ============================================================
// GEMM: out = X[M,K] @ W[N,K]^T   (M=4096, N=K=1024)
// MODE 0: plain out[m*N + n]                  (final O-proj)
// MODE 1: head layout [B,H,S,Dh] + RoPE       (Q, K proj)
// MODE 2: head layout [B,H,S,Dh], no RoPE     (V proj)
// 64x64 tile, BK=16, 256 threads, 4x4 per thread.
// Smem tiles stored k-major-transposed with stride 68 -> float4 reads.
// ============================================================
template<int MODE>
__global__ __launch_bounds__(256)
void gemm_proj_kernel(const float* __restrict__ X,
                      const float* __restrict__ W,
                      float* __restrict__ out)
{
    __shared__ float Xs[16 * 68];
    __shared__ float Ws[16 * 68];

    const int tid = threadIdx.x;
    const int ty  = tid >> 4;          // 0..15
    const int tx  = tid & 15;          // 0..15
    const int m0  = blockIdx.y * 64;
    const int n0  = blockIdx.x * 64;
    const int lr  = tid >> 2;          // 0..63  (load row)
    const int lc  = (tid & 3) << 2;    // 0,4,8,12 (load col base)

    float acc[4][4];
    #pragma unroll
    for (int i = 0; i < 4; i++)
        #pragma unroll
        for (int j = 0; j < 4; j++) acc[i][j] = 0.0f;

    for (int k0 = 0; k0 < DMODEL; k0 += 16) {
        float4 xv = *reinterpret_cast<const float4*>(&X[(m0 + lr) * DMODEL + k0 + lc]);
        float4 wv = *reinterpret_cast<const float4*>(&W[(n0 + lr) * DMODEL + k0 + lc]);
        Xs[(lc + 0) * 68 + lr] = xv.x;
        Xs[(lc + 1) * 68 + lr] = xv.y;
        Xs[(lc + 2) * 68 + lr] = xv.z;
        Xs[(lc + 3) * 68 + lr] = xv.w;
        Ws[(lc + 0) * 68 + lr] = wv.x;
        Ws[(lc + 1) * 68 + lr] = wv.y;
        Ws[(lc + 2) * 68 + lr] = wv.z;
        Ws[(lc + 3) * 68 + lr] = wv.w;
        __syncthreads();

        #pragma unroll
        for (int kk = 0; kk < 16; kk++) {
            float a[4], b[4];
            *reinterpret_cast<float4*>(a) =
                *reinterpret_cast<const float4*>(&Xs[kk * 68 + (ty << 2)]);
            *reinterpret_cast<float4*>(b) =
                *reinterpret_cast<const float4*>(&Ws[kk * 68 + (tx << 2)]);
            #pragma unroll
            for (int i = 0; i < 4; i++)
                #pragma unroll
                for (int j = 0; j < 4; j++)
                    acc[i][j] = fmaf(a[i], b[j], acc[i][j]);
        }
        __syncthreads();
    }

    if (MODE == 0) {
        #pragma unroll
        for (int ii = 0; ii < 4; ii++) {
            int m = m0 + (ty << 2) + ii;
            float4 r = make_float4(acc[ii][0], acc[ii][1], acc[ii][2], acc[ii][3]);
            *reinterpret_cast<float4*>(&out[m * DMODEL + n0 + (tx << 2)]) = r;
        }
    } else {
        const int n  = n0 + (tx << 2);
        const int h  = n >> 6;
        const int d0 = n & 63;
        const int ip0 = d0 >> 1;       // pair index of (d0, d0+1)
        #pragma unroll
        for (int ii = 0; ii < 4; ii++) {
            int m = m0 + (ty << 2) + ii;
            int b = m / SEQ;
            int s = m % SEQ;
            float4 r;
            if (MODE == 1) {
                float c0 = g_cos[s * DHALF + ip0];
                float s0 = g_sin[s * DHALF + ip0];
                float c1 = g_cos[s * DHALF + ip0 + 1];
                float s1 = g_sin[s * DHALF + ip0 + 1];
                r.x = acc[ii][0] * c0 - acc[ii][1] * s0;
                r.y = acc[ii][0] * s0 + acc[ii][1] * c0;
                r.z = acc[ii][2] * c1 - acc[ii][3] * s1;
                r.w = acc[ii][2] * s1 + acc[ii][3] * c1;
            } else {
                r = make_float4(acc[ii][0], acc[ii][1], acc[ii][2], acc[ii][3]);
            }
            size_t idx = ((size_t)(b * NHEADS + h) * SEQ + s) * DHEAD + d0;
            *reinterpret_cast<float4*>(&out[idx]) = r;
        }
    }
}

// ============================================================
// Flash attention (fp32, causal). One block = (b*h, 64-query tile).
// 256 threads, 4x4 micro-tiles. Smem: Q^T, K^T, V, P^T each [*,68].
// ============================================================
__global__ __launch_bounds__(256)
void flash_attn_kernel(float* __restrict__ outA)
{
    extern __shared__ float sm[];
    float* Qs = sm;                 // transposed: Qs[d*68 + row]
    float* Ks = sm + 64 * 68;       // transposed: Ks[d*68 + row]
    float* Vs = sm + 2 * 64 * 68;   // natural:    Vs[row*68 + d]
    float* Ps = sm + 3 * 64 * 68;   // transposed: Ps[col*68 + row]

    const int tid = threadIdx.x;
    const int ty  = tid >> 4;
    const int tx  = tid & 15;
    const int qt  = blockIdx.x;         // query tile (0..31)
    const int bh  = blockIdx.y;         // b*H+h     (0..31)

    const float* Qg = g_Q + (size_t)bh * SEQ * DHEAD + (size_t)qt * 64 * DHEAD;
    const float* Kg = g_K + (size_t)bh * SEQ * DHEAD;
    const float* Vg = g_V + (size_t)bh * SEQ * DHEAD;

    // load Q tile (transposed)
    for (int e = tid; e < 64 * 16; e += 256) {
        int r  = e >> 4;
        int c4 = (e & 15) << 2;
        float4 v = *reinterpret_cast<const float4*>(&Qg[r * DHEAD + c4]);
        Qs[(c4 + 0) * 68 + r] = v.x;
        Qs[(c4 + 1) * 68 + r] = v.y;
        Qs[(c4 + 2) * 68 + r] = v.z;
        Qs[(c4 + 3) * 68 + r] = v.w;
    }

    float m_i[4], l_i[4], o[4][4];
    #pragma unroll
    for (int i = 0; i < 4; i++) {
        m_i[i] = -1e30f;
        l_i[i] = 0.0f;
        #pragma unroll
        for (int j = 0; j < 4; j++) o[i][j] = 0.0f;
    }

    const float scale = 0.125f;  // 1/sqrt(64)

    for (int kt = 0; kt <= qt; kt++) {
        const float* Kt = Kg + (size_t)kt * 64 * DHEAD;
        const float* Vt = Vg + (size_t)kt * 64 * DHEAD;
        for (int e = tid; e < 64 * 16; e += 256) {
            int r  = e >> 4;
            int c4 = (e & 15) << 2;
            float4 kv = *reinterpret_cast<const float4*>(&Kt[r * DHEAD + c4]);
            Ks[(c4 + 0) * 68 + r] = kv.x;
            Ks[(c4 + 1) * 68 + r] = kv.y;
            Ks[(c4 + 2) * 68 + r] = kv.z;
            Ks[(c4 + 3) * 68 + r] = kv.w;
            float4 vv = *reinterpret_cast<const float4*>(&Vt[r * DHEAD + c4]);
            *reinterpret_cast<float4*>(&Vs[r * 68 + c4]) = vv;
        }
        __syncthreads();

        // S = Q K^T * scale
        float sacc[4][4];
        #pragma unroll
        for (int i = 0; i < 4; i++)
            #pragma unroll
            for (int j = 0; j < 4; j++) sacc[i][j] = 0.0f;

        #pragma unroll 8
        for (int d = 0; d < 64; d++) {
            float qa[4], kb[4];
            *reinterpret_cast<float4*>(qa) =
                *reinterpret_cast<const float4*>(&Qs[d * 68 + (ty << 2)]);
            *reinterpret_cast<float4*>(kb) =
                *reinterpret_cast<const float4*>(&Ks[d * 68 + (tx << 2)]);
            #pragma unroll
            for (int i = 0; i < 4; i++)
                #pragma unroll
                for (int j = 0; j < 4; j++)
                    sacc[i][j] = fmaf(qa[i], kb[j], sacc[i][j]);
        }

        const bool diag = (kt == qt);
        #pragma unroll
        for (int ii = 0; ii < 4; ii++) {
            #pragma unroll
            for (int jj = 0; jj < 4; jj++) {
                float v = sacc[ii][jj] * scale;
                if (diag && ((tx << 2) + jj) > ((ty << 2) + ii)) v = -1e30f;
                sacc[ii][jj] = v;
            }
        }

        // online softmax per row (16-thread groups share a row set)
        #pragma unroll
        for (int ii = 0; ii < 4; ii++) {
            float rmax = fmaxf(fmaxf(sacc[ii][0], sacc[ii][1]),
                               fmaxf(sacc[ii][2], sacc[ii][3]));
            #pragma unroll
            for (int off = 8; off >= 1; off >>= 1)
                rmax = fmaxf(rmax, __shfl_xor_sync(0xffffffffu, rmax, off));
            float mnew = fmaxf(m_i[ii], rmax);

            float psum = 0.0f;
            #pragma unroll
            for (int jj = 0; jj < 4; jj++) {
                float p = __expf(sacc[ii][jj] - mnew);
                Ps[((tx << 2) + jj) * 68 + (ty << 2) + ii] = p;
                psum += p;
            }
            #pragma unroll
            for (int off = 8; off >= 1; off >>= 1)
                psum += __shfl_xor_sync(0xffffffffu, psum, off);

            float alpha = __expf(m_i[ii] - mnew);
            l_i[ii] = l_i[ii] * alpha + psum;
            m_i[ii] = mnew;
            #pragma unroll
            for (int jj = 0; jj < 4; jj++) o[ii][jj] *= alpha;
        }
        __syncthreads();

        // O += P @ V
        #pragma unroll 8
        for (int j = 0; j < 64; j++) {
            float pa[4], vb[4];
            *reinterpret_cast<float4*>(pa) =
                *reinterpret_cast<const float4*>(&Ps[j * 68 + (ty << 2)]);
            *reinterpret_cast<float4*>(vb) =
                *reinterpret_cast<const float4*>(&Vs[j * 68 + (tx << 2)]);
            #pragma unroll
            for (int i = 0; i < 4; i++)
                #pragma unroll
                for (int jj = 0; jj < 4; jj++)
                    o[i][jj] = fmaf(pa[i], vb[jj], o[i][jj]);
        }
        __syncthreads();
    }

    // write to [B*S, D] layout: col = h*64 + d
    const int b = bh >> 4;
    const int h = bh & 15;
    #pragma unroll
    for (int ii = 0; ii < 4; ii++) {
        int s = qt * 64 + (ty << 2) + ii;
        float inv_l = 1.0f / l_i[ii];
        float4 r = make_float4(o[ii][0] * inv_l, o[ii][1] * inv_l,
                               o[ii][2] * inv_l, o[ii][3] * inv_l);
        size_t idx = ((size_t)b * SEQ + s) * DMODEL + h * DHEAD + (tx << 2);
        *reinterpret_cast<float4*>(&outA[idx]) = r;
    }
}

// ============================================================
extern "C" void kernel_launch(void* const* d_in, const int* in_sizes, int n_in,
                              void* d_out, int out_size) {
    const float* x  = (const float*)d_in[0];
    const int*   tp = (const int*)  d_in[1];
    const float* Wq = (const float*)d_in[2];
    const float* Wk = (const float*)d_in[3];
    const float* Wv = (const float*)d_in[4];
    const float* Wo = (const float*)d_in[5];
    float* out = (float*)d_out;

    float *gq, *gk, *gv, *ga;
    cudaGetSymbolAddress((void**)&gq, g_Q);
    cudaGetSymbolAddress((void**)&gk, g_K);
    cudaGetSymbolAddress((void**)&gv, g_V);
    cudaGetSymbolAddress((void**)&ga, g_A);

    rope_table_kernel<<<(SEQ * DHALF + 255) / 256, 256>>>(tp);

    dim3 ggrid(DMODEL / 64, MROWS / 64);
    gemm_proj_kernel<1><<<ggrid, 256>>>(x, Wq, gq);
    gemm_proj_kernel<1><<<ggrid, 256>>>(x, Wk, gk);
    gemm_proj_kernel<2><<<ggrid, 256>>>(x, Wv, gv);

    const int smem = 4 * 64 * 68 * sizeof(float);  // 69632 B
    cudaFuncSetAttribute(flash_attn_kernel,
                         cudaFuncAttributeMaxDynamicSharedMemorySize, smem);
    flash_attn_kernel<<<dim3(SEQ / 64, BATCH * NHEADS), 256, smem>>>(ga);

    gemm_proj_kernel<0><<<ggrid, 256>>>(ga, Wo, out);
}

// round 5
// speedup vs baseline: 1.1677x; 1.1677x over previous
#include <cuda_runtime.h>
#include <math.h>

#define BATCH   2
#define SEQ     2048
#define DMODEL  1024
#define NHEADS  16
#define DHEAD   64
#define DHALF   32
#define MROWS   (BATCH*SEQ)   // 4096

// ---- scratch (allocation-free: __device__ globals) ----
static __device__ float g_Q[BATCH*NHEADS*SEQ*DHEAD];   // 16 MB
static __device__ float g_K[BATCH*NHEADS*SEQ*DHEAD];   // 16 MB
static __device__ float g_V[BATCH*NHEADS*SEQ*DHEAD];   // 16 MB
static __device__ float g_A[MROWS*DMODEL];             // 16 MB
static __device__ float g_cos[SEQ*DHALF];
static __device__ float g_sin[SEQ*DHALF];

// ============================================================
// RoPE table
// ============================================================
__global__ void rope_table_kernel(const int* __restrict__ tpos) {
    int idx = blockIdx.x * blockDim.x + threadIdx.x;
    if (idx >= SEQ * DHALF) return;
    int s = idx >> 5;
    int i = idx & 31;
    double freq = exp(-0.28782313662425572 * (double)i);  // theta^{-i/32}
    float ang = (float)((double)tpos[s] * freq);
    float sn, cs;
    sincosf(ang, &sn, &cs);
    g_cos[idx] = cs;
    g_sin[idx] = sn;
}

// ============================================================
// GEMM: out = X[M,K] @ W[N,K]^T   (M=4096, N=K=1024)
// 128x128 tile, BK=16, 256 threads, 8x8 per thread.
// Register-prefetched global loads; smem transposed, stride 132.
// MODE 0: plain [M,N]; MODE 1: head layout + RoPE; MODE 2: head layout.
// ============================================================
template<int MODE>
__global__ __launch_bounds__(256, 2)
void gemm_proj_kernel(const float* __restrict__ X,
                      const float* __restrict__ W,
                      float* __restrict__ out)
{
    __shared__ float Xs[16 * 132];
    __shared__ float Ws[16 * 132];

    const int tid = threadIdx.x;
    const int ty  = tid >> 4;            // 0..15
    const int tx  = tid & 15;            // 0..15
    const int m0  = blockIdx.y * 128;
    const int n0  = blockIdx.x * 128;
    const int lr  = tid >> 1;            // 0..127
    const int lc  = (tid & 1) << 3;      // 0 or 8

    const float* Xp = X + (size_t)(m0 + lr) * DMODEL + lc;
    const float* Wp = W + (size_t)(n0 + lr) * DMODEL + lc;

    float4 xv0 = *reinterpret_cast<const float4*>(Xp);
    float4 xv1 = *reinterpret_cast<const float4*>(Xp + 4);
    float4 wv0 = *reinterpret_cast<const float4*>(Wp);
    float4 wv1 = *reinterpret_cast<const float4*>(Wp + 4);

    float acc[8][8];
    #pragma unroll
    for (int i = 0; i < 8; i++)
        #pragma unroll
        for (int j = 0; j < 8; j++) acc[i][j] = 0.0f;

    for (int k0 = 0; k0 < DMODEL; k0 += 16) {
        Xs[(lc + 0) * 132 + lr] = xv0.x;
        Xs[(lc + 1) * 132 + lr] = xv0.y;
        Xs[(lc + 2) * 132 + lr] = xv0.z;
        Xs[(lc + 3) * 132 + lr] = xv0.w;
        Xs[(lc + 4) * 132 + lr] = xv1.x;
        Xs[(lc + 5) * 132 + lr] = xv1.y;
        Xs[(lc + 6) * 132 + lr] = xv1.z;
        Xs[(lc + 7) * 132 + lr] = xv1.w;
        Ws[(lc + 0) * 132 + lr] = wv0.x;
        Ws[(lc + 1) * 132 + lr] = wv0.y;
        Ws[(lc + 2) * 132 + lr] = wv0.z;
        Ws[(lc + 3) * 132 + lr] = wv0.w;
        Ws[(lc + 4) * 132 + lr] = wv1.x;
        Ws[(lc + 5) * 132 + lr] = wv1.y;
        Ws[(lc + 6) * 132 + lr] = wv1.z;
        Ws[(lc + 7) * 132 + lr] = wv1.w;
        __syncthreads();

        if (k0 + 16 < DMODEL) {
            xv0 = *reinterpret_cast<const float4*>(Xp + k0 + 16);
            xv1 = *reinterpret_cast<const float4*>(Xp + k0 + 20);
            wv0 = *reinterpret_cast<const float4*>(Wp + k0 + 16);
            wv1 = *reinterpret_cast<const float4*>(Wp + k0 + 20);
        }

        #pragma unroll
        for (int kk = 0; kk < 16; kk++) {
            float a[8], b[8];
            *reinterpret_cast<float4*>(a) =
                *reinterpret_cast<const float4*>(&Xs[kk * 132 + (ty << 3)]);
            *reinterpret_cast<float4*>(a + 4) =
                *reinterpret_cast<const float4*>(&Xs[kk * 132 + (ty << 3) + 4]);
            *reinterpret_cast<float4*>(b) =
                *reinterpret_cast<const float4*>(&Ws[kk * 132 + (tx << 3)]);
            *reinterpret_cast<float4*>(b + 4) =
                *reinterpret_cast<const float4*>(&Ws[kk * 132 + (tx << 3) + 4]);
            #pragma unroll
            for (int i = 0; i < 8; i++)
                #pragma unroll
                for (int j = 0; j < 8; j++)
                    acc[i][j] = fmaf(a[i], b[j], acc[i][j]);
        }
        __syncthreads();
    }

    if (MODE == 0) {
        #pragma unroll
        for (int ii = 0; ii < 8; ii++) {
            int m = m0 + (ty << 3) + ii;
            float* o = &out[(size_t)m * DMODEL + n0 + (tx << 3)];
            *reinterpret_cast<float4*>(o) =
                make_float4(acc[ii][0], acc[ii][1], acc[ii][2], acc[ii][3]);
            *reinterpret_cast<float4*>(o + 4) =
                make_float4(acc[ii][4], acc[ii][5], acc[ii][6], acc[ii][7]);
        }
    } else {
        const int n   = n0 + (tx << 3);
        const int h   = n >> 6;
        const int d0  = n & 63;
        const int ip0 = d0 >> 1;   // 4 consecutive pairs
        #pragma unroll
        for (int ii = 0; ii < 8; ii++) {
            int m = m0 + (ty << 3) + ii;
            int b = m >> 11;          // / SEQ
            int s = m & (SEQ - 1);
            float r[8];
            if (MODE == 1) {
                #pragma unroll
                for (int p = 0; p < 4; p++) {
                    float c = g_cos[s * DHALF + ip0 + p];
                    float sn = g_sin[s * DHALF + ip0 + p];
                    float e = acc[ii][2 * p];
                    float o2 = acc[ii][2 * p + 1];
                    r[2 * p]     = e * c - o2 * sn;
                    r[2 * p + 1] = e * sn + o2 * c;
                }
            } else {
                #pragma unroll
                for (int j = 0; j < 8; j++) r[j] = acc[ii][j];
            }
            size_t idx = ((size_t)(b * NHEADS + h) * SEQ + s) * DHEAD + d0;
            *reinterpret_cast<float4*>(&out[idx]) =
                make_float4(r[0], r[1], r[2], r[3]);
            *reinterpret_cast<float4*>(&out[idx + 4]) =
                make_float4(r[4], r[5], r[6], r[7]);
        }
    }
}

// ============================================================
// Flash attention (fp32, causal). Block = (b*h, 128-query tile).
// 256 threads. S tile: 128x128 (8x8 per thread).
// O tile: 128x64 (8x4 per thread, cols tx*4).
// Smem: Q^T[64][132], K^T[64][132], V[128][68], P[128][132].
// ============================================================
__global__ __launch_bounds__(256, 1)
void flash_attn_kernel(float* __restrict__ outA)
{
    extern __shared__ float sm[];
    float* Qs = sm;                     // transposed: Qs[d*132 + q]
    float* Ks = Qs + 64 * 132;          // transposed: Ks[d*132 + k]
    float* Vs = Ks + 64 * 132;          // natural:    Vs[k*68 + d]
    float* Ps = Vs + 128 * 68;          // natural:    Ps[q*132 + k]

    const int tid = threadIdx.x;
    const int ty  = tid >> 4;           // 0..15 -> q rows ty*8..+8
    const int tx  = tid & 15;           // 0..15
    const int qt  = (gridDim.x - 1) - blockIdx.x;   // big tiles first
    const int bh  = blockIdx.y;

    const float* Qg = g_Q + (size_t)bh * SEQ * DHEAD + (size_t)qt * 128 * DHEAD;
    const float* Kg = g_K + (size_t)bh * SEQ * DHEAD;
    const float* Vg = g_V + (size_t)bh * SEQ * DHEAD;

    const float scale = 0.125f;   // 1/sqrt(64), folded into Q

    // load Q tile transposed, pre-scaled
    for (int e = tid; e < 128 * 16; e += 256) {
        int r  = e >> 4;
        int c4 = (e & 15) << 2;
        float4 v = *reinterpret_cast<const float4*>(&Qg[r * DHEAD + c4]);
        Qs[(c4 + 0) * 132 + r] = v.x * scale;
        Qs[(c4 + 1) * 132 + r] = v.y * scale;
        Qs[(c4 + 2) * 132 + r] = v.z * scale;
        Qs[(c4 + 3) * 132 + r] = v.w * scale;
    }

    float m_i[8], l_i[8], o[8][4];
    #pragma unroll
    for (int i = 0; i < 8; i++) {
        m_i[i] = -1e30f;
        l_i[i] = 0.0f;
        #pragma unroll
        for (int j = 0; j < 4; j++) o[i][j] = 0.0f;
    }

    for (int kt = 0; kt <= qt; kt++) {
        const float* Kt = Kg + (size_t)kt * 128 * DHEAD;
        const float* Vt = Vg + (size_t)kt * 128 * DHEAD;
        for (int e = tid; e < 128 * 16; e += 256) {
            int r  = e >> 4;
            int c4 = (e & 15) << 2;
            float4 kv = *reinterpret_cast<const float4*>(&Kt[r * DHEAD + c4]);
            Ks[(c4 + 0) * 132 + r] = kv.x;
            Ks[(c4 + 1) * 132 + r] = kv.y;
            Ks[(c4 + 2) * 132 + r] = kv.z;
            Ks[(c4 + 3) * 132 + r] = kv.w;
            float4 vv = *reinterpret_cast<const float4*>(&Vt[r * DHEAD + c4]);
            *reinterpret_cast<float4*>(&Vs[r * 68 + c4]) = vv;
        }
        __syncthreads();

        // S = Q K^T (scale already in Q); S cols for this thread: tx*8..+8
        float sacc[8][8];
        #pragma unroll
        for (int i = 0; i < 8; i++)
            #pragma unroll
            for (int j = 0; j < 8; j++) sacc[i][j] = 0.0f;

        #pragma unroll 4
        for (int d = 0; d < 64; d++) {
            float qa[8], kb[8];
            *reinterpret_cast<float4*>(qa) =
                *reinterpret_cast<const float4*>(&Qs[d * 132 + (ty << 3)]);
            *reinterpret_cast<float4*>(qa + 4) =
                *reinterpret_cast<const float4*>(&Qs[d * 132 + (ty << 3) + 4]);
            *reinterpret_cast<float4*>(kb) =
                *reinterpret_cast<const float4*>(&Ks[d * 132 + (tx << 3)]);
            *reinterpret_cast<float4*>(kb + 4) =
                *reinterpret_cast<const float4*>(&Ks[d * 132 + (tx << 3) + 4]);
            #pragma unroll
            for (int i = 0; i < 8; i++)
                #pragma unroll
                for (int j = 0; j < 8; j++)
                    sacc[i][j] = fmaf(qa[i], kb[j], sacc[i][j]);
        }

        if (kt == qt) {
            #pragma unroll
            for (int ii = 0; ii < 8; ii++) {
                int ql = (ty << 3) + ii;
                #pragma unroll
                for (int jj = 0; jj < 8; jj++) {
                    if (((tx << 3) + jj) > ql) sacc[ii][jj] = -1e30f;
                }
            }
        }

        // online softmax (each row shared by the 16 lanes with equal ty)
        #pragma unroll
        for (int ii = 0; ii < 8; ii++) {
            float rmax = sacc[ii][0];
            #pragma unroll
            for (int jj = 1; jj < 8; jj++) rmax = fmaxf(rmax, sacc[ii][jj]);
            #pragma unroll
            for (int off = 8; off >= 1; off >>= 1)
                rmax = fmaxf(rmax, __shfl_xor_sync(0xffffffffu, rmax, off));
            float mnew = fmaxf(m_i[ii], rmax);

            float p[8], psum = 0.0f;
            #pragma unroll
            for (int jj = 0; jj < 8; jj++) {
                p[jj] = __expf(sacc[ii][jj] - mnew);
                psum += p[jj];
            }
            float* pr = &Ps[((ty << 3) + ii) * 132 + (tx << 3)];
            *reinterpret_cast<float4*>(pr) = make_float4(p[0], p[1], p[2], p[3]);
            *reinterpret_cast<float4*>(pr + 4) = make_float4(p[4], p[5], p[6], p[7]);

            #pragma unroll
            for (int off = 8; off >= 1; off >>= 1)
                psum += __shfl_xor_sync(0xffffffffu, psum, off);

            float alpha = __expf(m_i[ii] - mnew);
            l_i[ii] = l_i[ii] * alpha + psum;
            m_i[ii] = mnew;
            #pragma unroll
            for (int jj = 0; jj < 4; jj++) o[ii][jj] *= alpha;
        }
        __syncthreads();

        // O += P @ V ; O cols for this thread: tx*4..+4 (<= 60, inside DHEAD)
        #pragma unroll 4
        for (int k = 0; k < 128; k++) {
            float vb[4];
            *reinterpret_cast<float4*>(vb) =
                *reinterpret_cast<const float4*>(&Vs[k * 68 + (tx << 2)]);
            #pragma unroll
            for (int i = 0; i < 8; i++) {
                float pa = Ps[((ty << 3) + i) * 132 + k];
                #pragma unroll
                for (int j = 0; j < 4; j++)
                    o[i][j] = fmaf(pa, vb[j], o[i][j]);
            }
        }
        __syncthreads();
    }

    // write to [B*S, D]: col = h*64 + tx*4
    const int b = bh >> 4;
    const int h = bh & 15;
    #pragma unroll
    for (int ii = 0; ii < 8; ii++) {
        int s = qt * 128 + (ty << 3) + ii;
        float inv_l = 1.0f / l_i[ii];
        size_t idx = ((size_t)b * SEQ + s) * DMODEL + h * DHEAD + (tx << 2);
        *reinterpret_cast<float4*>(&outA[idx]) =
            make_float4(o[ii][0] * inv_l, o[ii][1] * inv_l,
                        o[ii][2] * inv_l, o[ii][3] * inv_l);
    }
}

// ============================================================
extern "C" void kernel_launch(void* const* d_in, const int* in_sizes, int n_in,
                              void* d_out, int out_size) {
    const float* x  = (const float*)d_in[0];
    const int*   tp = (const int*)  d_in[1];
    const float* Wq = (const float*)d_in[2];
    const float* Wk = (const float*)d_in[3];
    const float* Wv = (const float*)d_in[4];
    const float* Wo = (const float*)d_in[5];
    float* out = (float*)d_out;

    float *gq, *gk, *gv, *ga;
    cudaGetSymbolAddress((void**)&gq, g_Q);
    cudaGetSymbolAddress((void**)&gk, g_K);
    cudaGetSymbolAddress((void**)&gv, g_V);
    cudaGetSymbolAddress((void**)&ga, g_A);

    rope_table_kernel<<<(SEQ * DHALF + 255) / 256, 256>>>(tp);

    dim3 ggrid(DMODEL / 128, MROWS / 128);
    gemm_proj_kernel<1><<<ggrid, 256>>>(x, Wq, gq);
    gemm_proj_kernel<1><<<ggrid, 256>>>(x, Wk, gk);
    gemm_proj_kernel<2><<<ggrid, 256>>>(x, Wv, gv);

    const int smem = (64 * 132 + 64 * 132 + 128 * 68 + 128 * 132) * sizeof(float);
    cudaFuncSetAttribute(flash_attn_kernel,
                         cudaFuncAttributeMaxDynamicSharedMemorySize, smem);
    flash_attn_kernel<<<dim3(SEQ / 128, BATCH * NHEADS), 256, smem>>>(ga);

    gemm_proj_kernel<0><<<ggrid, 256>>>(ga, Wo, out);
}

// round 9
// speedup vs baseline: 1.6665x; 1.4271x over previous
#include <cuda_runtime.h>
#include <cuda_bf16.h>
#include <cstdint>
#include <math.h>

#define BATCH   2
#define SEQ     2048
#define DMODEL  1024
#define NHEADS  16
#define DHEAD   64
#define DHALF   32
#define MROWS   (BATCH*SEQ)   // 4096

// ---- scratch (allocation-free: __device__ globals) ----
static __device__ float g_Q[BATCH*NHEADS*SEQ*DHEAD];
static __device__ float g_K[BATCH*NHEADS*SEQ*DHEAD];
static __device__ float g_V[BATCH*NHEADS*SEQ*DHEAD];
static __device__ float g_A[MROWS*DMODEL];
static __device__ float g_cos[SEQ*DHALF];
static __device__ float g_sin[SEQ*DHALF];
static __device__ __nv_bfloat16 g_hiX[MROWS*DMODEL];
static __device__ __nv_bfloat16 g_loX[MROWS*DMODEL];
static __device__ __nv_bfloat16 g_hiW[DMODEL*DMODEL];
static __device__ __nv_bfloat16 g_loW[DMODEL*DMODEL];

// ================= portable PTX helpers (compute_103-safe) =================
__device__ __forceinline__ uint32_t smem_u32(const void* p) {
    uint32_t a;
    asm("{ .reg .u64 t; cvta.to.shared.u64 t, %1; cvt.u32.u64 %0, t; }"
        : "=r"(a) : "l"(p));
    return a;
}
__device__ __forceinline__ void cp16(uint32_t dst, const void* src) {
    uint64_t g;
    asm("cvta.to.global.u64 %0, %1;" : "=l"(g) : "l"(src));
    asm volatile("cp.async.cg.shared.global [%0], [%1], 16;" :: "r"(dst), "l"(g));
}
#define CP_COMMIT() asm volatile("cp.async.commit_group;" ::: "memory")
#define CP_WAIT0()  asm volatile("cp.async.wait_group 0;" ::: "memory")

__device__ __forceinline__ void ldsm_x4(uint32_t* r, uint32_t addr) {
    asm volatile("ldmatrix.sync.aligned.m8n8.x4.shared.b16 {%0,%1,%2,%3}, [%4];"
        : "=r"(r[0]), "=r"(r[1]), "=r"(r[2]), "=r"(r[3]) : "r"(addr));
}
__device__ __forceinline__ void mma_bf16(float* d, const uint32_t* a,
                                         uint32_t b0, uint32_t b1) {
    asm volatile("mma.sync.aligned.m16n8k16.row.col.f32.bf16.bf16.f32 "
        "{%0,%1,%2,%3}, {%4,%5,%6,%7}, {%8,%9}, {%0,%1,%2,%3};"
        : "+f"(d[0]), "+f"(d[1]), "+f"(d[2]), "+f"(d[3])
        : "r"(a[0]), "r"(a[1]), "r"(a[2]), "r"(a[3]), "r"(b0), "r"(b1));
}

// ============================================================
// RoPE table
// ============================================================
__global__ void rope_table_kernel(const int* __restrict__ tpos) {
    int idx = blockIdx.x * blockDim.x + threadIdx.x;
    if (idx >= SEQ * DHALF) return;
    int s = idx >> 5;
    int i = idx & 31;
    double freq = exp(-0.28782313662425572 * (double)i);
    float ang = (float)((double)tpos[s] * freq);
    float sn, cs;
    sincosf(ang, &sn, &cs);
    g_cos[idx] = cs;
    g_sin[idx] = sn;
}

// ============================================================
// fp32 -> (hi, lo) bf16 split
// ============================================================
__global__ void split_kernel(const float* __restrict__ src,
                             __nv_bfloat16* __restrict__ hi,
                             __nv_bfloat16* __restrict__ lo, int n) {
    int i = blockIdx.x * blockDim.x + threadIdx.x;
    if (i >= n) return;
    float f = src[i];
    __nv_bfloat16 h = __float2bfloat16(f);
    hi[i] = h;
    lo[i] = __float2bfloat16(f - __bfloat162float(h));
}

// ============================================================
// HMMA split-bf16 GEMM: out = X[M,K] @ W[N,K]^T
// 128x128 CTA tile, 8 warps (4x2, warp tile 32x64), BK=32,
// double-buffered cp.async. Smem rows padded to 80B (conflict-free
// ldmatrix). acc = Xhi@Whi + Xlo@Whi + Xhi@Wlo (fp32 accum).
// MODE 0: plain [M,N]; MODE 1: head layout + RoPE; MODE 2: head layout.
// ============================================================
#define BK      32
#define TROW    40                     // bf16 per smem row (80 B)
#define TILE_B  (128*TROW*2)           // 10240 B per tile
#define BUF_B   (4*TILE_B)             // Ahi|Alo|Bhi|Blo = 40960 B
#define NIT     (DMODEL/BK)            // 32

template<int MODE>
__global__ __launch_bounds__(256)
void mma_gemm_kernel(const __nv_bfloat16* __restrict__ Ahi,
                     const __nv_bfloat16* __restrict__ Alo,
                     const __nv_bfloat16* __restrict__ Bhi,
                     const __nv_bfloat16* __restrict__ Blo,
                     float* __restrict__ out)
{
    extern __shared__ char smem[];
    const uint32_t sbase = smem_u32(smem);

    const int tid  = threadIdx.x;
    const int wid  = tid >> 5;
    const int lane = tid & 31;
    const int wm   = wid >> 1;          // 0..3 -> m offset wm*32
    const int wn   = wid & 1;           // 0..1 -> n offset wn*64
    const int m0   = blockIdx.y * 128;
    const int n0   = blockIdx.x * 128;

    const __nv_bfloat16* gsrc[4] = {
        Ahi + (size_t)m0 * DMODEL, Alo + (size_t)m0 * DMODEL,
        Bhi + (size_t)n0 * DMODEL, Blo + (size_t)n0 * DMODEL };

    // per-thread load slots: 2 x 16B per tile (512 slots / 256 threads)
    const int r0 = tid >> 2;            // rows for slot 0 (0..63)
    const int c0 = tid & 3;             // chunk 0..3
    // slot1: idx = tid+256 -> row 64 + r0, same chunk

    float acc[2][8][4];
    #pragma unroll
    for (int mt = 0; mt < 2; mt++)
        #pragma unroll
        for (int nt = 0; nt < 8; nt++)
            #pragma unroll
            for (int q = 0; q < 4; q++) acc[mt][nt][q] = 0.0f;

    // ---- prologue load ----
    {
        uint32_t sb = sbase;
        #pragma unroll
        for (int t = 0; t < 4; t++) {
            cp16(sb + t * TILE_B + (r0 * TROW + c0 * 8) * 2,
                 gsrc[t] + (size_t)r0 * DMODEL + c0 * 8);
            cp16(sb + t * TILE_B + ((r0 + 64) * TROW + c0 * 8) * 2,
                 gsrc[t] + (size_t)(r0 + 64) * DMODEL + c0 * 8);
        }
        CP_COMMIT();
        CP_WAIT0();
        __syncthreads();
    }

    // ldmatrix lane address components
    const int a_row   = wm * 32 + (lane & 15);
    const int a_ch    = lane >> 4;                       // 0/1 within kstep
    const int b_rowl  = ((lane >> 4) << 3) + (lane & 7); // 0..15
    const int b_ch    = (lane >> 3) & 1;

    for (int it = 0; it < NIT; it++) {
        if (it + 1 < NIT) {
            uint32_t sb = sbase + ((it + 1) & 1) * BUF_B;
            const int k0 = (it + 1) * BK;
            #pragma unroll
            for (int t = 0; t < 4; t++) {
                cp16(sb + t * TILE_B + (r0 * TROW + c0 * 8) * 2,
                     gsrc[t] + (size_t)r0 * DMODEL + k0 + c0 * 8);
                cp16(sb + t * TILE_B + ((r0 + 64) * TROW + c0 * 8) * 2,
                     gsrc[t] + (size_t)(r0 + 64) * DMODEL + k0 + c0 * 8);
            }
            CP_COMMIT();
        }

        const uint32_t sb = sbase + (it & 1) * BUF_B;
        #pragma unroll
        for (int ks = 0; ks < 2; ks++) {
            uint32_t ahi[2][4], alo[2][4];
            #pragma unroll
            for (int mt = 0; mt < 2; mt++) {
                uint32_t addr = sb + ((a_row + mt * 16) * TROW) * 2
                              + (ks * 2 + a_ch) * 16;
                ldsm_x4(ahi[mt], addr);
                ldsm_x4(alo[mt], addr + TILE_B);
            }
            #pragma unroll
            for (int ntp = 0; ntp < 4; ntp++) {
                uint32_t baddr = sb + 2 * TILE_B
                    + ((wn * 64 + ntp * 16 + b_rowl) * TROW) * 2
                    + (ks * 2 + b_ch) * 16;
                uint32_t bh[4], bl[4];
                ldsm_x4(bh, baddr);
                ldsm_x4(bl, baddr + TILE_B);
                #pragma unroll
                for (int sub = 0; sub < 2; sub++) {
                    const int nt = ntp * 2 + sub;
                    uint32_t p0 = bh[sub * 2], p1 = bh[sub * 2 + 1];
                    mma_bf16(acc[0][nt], ahi[0], p0, p1);
                    mma_bf16(acc[1][nt], ahi[1], p0, p1);
                    mma_bf16(acc[0][nt], alo[0], p0, p1);
                    mma_bf16(acc[1][nt], alo[1], p0, p1);
                    uint32_t q0 = bl[sub * 2], q1 = bl[sub * 2 + 1];
                    mma_bf16(acc[0][nt], ahi[0], q0, q1);
                    mma_bf16(acc[1][nt], ahi[1], q0, q1);
                }
            }
        }
        if (it + 1 < NIT) CP_WAIT0();
        __syncthreads();
    }

    // ---- epilogue: direct fragment stores ----
    const int gid = lane >> 2;
    const int tig = lane & 3;
    #pragma unroll
    for (int mt = 0; mt < 2; mt++) {
        #pragma unroll
        for (int nt = 0; nt < 8; nt++) {
            const int n = n0 + wn * 64 + nt * 8 + tig * 2;
            #pragma unroll
            for (int half = 0; half < 2; half++) {
                const int m = m0 + wm * 32 + mt * 16 + gid + half * 8;
                float x = acc[mt][nt][half * 2];
                float y = acc[mt][nt][half * 2 + 1];
                if (MODE == 0) {
                    *reinterpret_cast<float2*>(&out[(size_t)m * DMODEL + n]) =
                        make_float2(x, y);
                } else {
                    const int b  = m >> 11;
                    const int s  = m & (SEQ - 1);
                    const int h  = n >> 6;
                    const int d0 = n & 63;
                    if (MODE == 1) {
                        float cs = g_cos[s * DHALF + (d0 >> 1)];
                        float sn = g_sin[s * DHALF + (d0 >> 1)];
                        float rx = x * cs - y * sn;
                        float ry = x * sn + y * cs;
                        x = rx; y = ry;
                    }
                    size_t idx = (((size_t)(b * NHEADS + h)) * SEQ + s) * DHEAD + d0;
                    *reinterpret_cast<float2*>(&out[idx]) = make_float2(x, y);
                }
            }
        }
    }
}

// ============================================================
// Flash attention (fp32, causal) — unchanged from round 5
// ============================================================
__global__ __launch_bounds__(256, 1)
void flash_attn_kernel(float* __restrict__ outA)
{
    extern __shared__ float sm[];
    float* Qs = sm;
    float* Ks = Qs + 64 * 132;
    float* Vs = Ks + 64 * 132;
    float* Ps = Vs + 128 * 68;

    const int tid = threadIdx.x;
    const int ty  = tid >> 4;
    const int tx  = tid & 15;
    const int qt  = (gridDim.x - 1) - blockIdx.x;
    const int bh  = blockIdx.y;

    const float* Qg = g_Q + (size_t)bh * SEQ * DHEAD + (size_t)qt * 128 * DHEAD;
    const float* Kg = g_K + (size_t)bh * SEQ * DHEAD;
    const float* Vg = g_V + (size_t)bh * SEQ * DHEAD;

    const float scale = 0.125f;

    for (int e = tid; e < 128 * 16; e += 256) {
        int r  = e >> 4;
        int c4 = (e & 15) << 2;
        float4 v = *reinterpret_cast<const float4*>(&Qg[r * DHEAD + c4]);
        Qs[(c4 + 0) * 132 + r] = v.x * scale;
        Qs[(c4 + 1) * 132 + r] = v.y * scale;
        Qs[(c4 + 2) * 132 + r] = v.z * scale;
        Qs[(c4 + 3) * 132 + r] = v.w * scale;
    }

    float m_i[8], l_i[8], o[8][4];
    #pragma unroll
    for (int i = 0; i < 8; i++) {
        m_i[i] = -1e30f;
        l_i[i] = 0.0f;
        #pragma unroll
        for (int j = 0; j < 4; j++) o[i][j] = 0.0f;
    }

    for (int kt = 0; kt <= qt; kt++) {
        const float* Kt = Kg + (size_t)kt * 128 * DHEAD;
        const float* Vt = Vg + (size_t)kt * 128 * DHEAD;
        for (int e = tid; e < 128 * 16; e += 256) {
            int r  = e >> 4;
            int c4 = (e & 15) << 2;
            float4 kv = *reinterpret_cast<const float4*>(&Kt[r * DHEAD + c4]);
            Ks[(c4 + 0) * 132 + r] = kv.x;
            Ks[(c4 + 1) * 132 + r] = kv.y;
            Ks[(c4 + 2) * 132 + r] = kv.z;
            Ks[(c4 + 3) * 132 + r] = kv.w;
            float4 vv = *reinterpret_cast<const float4*>(&Vt[r * DHEAD + c4]);
            *reinterpret_cast<float4*>(&Vs[r * 68 + c4]) = vv;
        }
        __syncthreads();

        float sacc[8][8];
        #pragma unroll
        for (int i = 0; i < 8; i++)
            #pragma unroll
            for (int j = 0; j < 8; j++) sacc[i][j] = 0.0f;

        #pragma unroll 4
        for (int d = 0; d < 64; d++) {
            float qa[8], kb[8];
            *reinterpret_cast<float4*>(qa) =
                *reinterpret_cast<const float4*>(&Qs[d * 132 + (ty << 3)]);
            *reinterpret_cast<float4*>(qa + 4) =
                *reinterpret_cast<const float4*>(&Qs[d * 132 + (ty << 3) + 4]);
            *reinterpret_cast<float4*>(kb) =
                *reinterpret_cast<const float4*>(&Ks[d * 132 + (tx << 3)]);
            *reinterpret_cast<float4*>(kb + 4) =
                *reinterpret_cast<const float4*>(&Ks[d * 132 + (tx << 3) + 4]);
            #pragma unroll
            for (int i = 0; i < 8; i++)
                #pragma unroll
                for (int j = 0; j < 8; j++)
                    sacc[i][j] = fmaf(qa[i], kb[j], sacc[i][j]);
        }

        if (kt == qt) {
            #pragma unroll
            for (int ii = 0; ii < 8; ii++) {
                int ql = (ty << 3) + ii;
                #pragma unroll
                for (int jj = 0; jj < 8; jj++)
                    if (((tx << 3) + jj) > ql) sacc[ii][jj] = -1e30f;
            }
        }

        #pragma unroll
        for (int ii = 0; ii < 8; ii++) {
            float rmax = sacc[ii][0];
            #pragma unroll
            for (int jj = 1; jj < 8; jj++) rmax = fmaxf(rmax, sacc[ii][jj]);
            #pragma unroll
            for (int off = 8; off >= 1; off >>= 1)
                rmax = fmaxf(rmax, __shfl_xor_sync(0xffffffffu, rmax, off));
            float mnew = fmaxf(m_i[ii], rmax);

            float p[8], psum = 0.0f;
            #pragma unroll
            for (int jj = 0; jj < 8; jj++) {
                p[jj] = __expf(sacc[ii][jj] - mnew);
                psum += p[jj];
            }
            float* pr = &Ps[((ty << 3) + ii) * 132 + (tx << 3)];
            *reinterpret_cast<float4*>(pr) = make_float4(p[0], p[1], p[2], p[3]);
            *reinterpret_cast<float4*>(pr + 4) = make_float4(p[4], p[5], p[6], p[7]);

            #pragma unroll
            for (int off = 8; off >= 1; off >>= 1)
                psum += __shfl_xor_sync(0xffffffffu, psum, off);

            float alpha = __expf(m_i[ii] - mnew);
            l_i[ii] = l_i[ii] * alpha + psum;
            m_i[ii] = mnew;
            #pragma unroll
            for (int jj = 0; jj < 4; jj++) o[ii][jj] *= alpha;
        }
        __syncthreads();

        #pragma unroll 4
        for (int k = 0; k < 128; k++) {
            float vb[4];
            *reinterpret_cast<float4*>(vb) =
                *reinterpret_cast<const float4*>(&Vs[k * 68 + (tx << 2)]);
            #pragma unroll
            for (int i = 0; i < 8; i++) {
                float pa = Ps[((ty << 3) + i) * 132 + k];
                #pragma unroll
                for (int j = 0; j < 4; j++)
                    o[i][j] = fmaf(pa, vb[j], o[i][j]);
            }
        }
        __syncthreads();
    }

    const int b = bh >> 4;
    const int h = bh & 15;
    #pragma unroll
    for (int ii = 0; ii < 8; ii++) {
        int s = qt * 128 + (ty << 3) + ii;
        float inv_l = 1.0f / l_i[ii];
        size_t idx = ((size_t)b * SEQ + s) * DMODEL + h * DHEAD + (tx << 2);
        *reinterpret_cast<float4*>(&outA[idx]) =
            make_float4(o[ii][0] * inv_l, o[ii][1] * inv_l,
                        o[ii][2] * inv_l, o[ii][3] * inv_l);
    }
}

// ============================================================
extern "C" void kernel_launch(void* const* d_in, const int* in_sizes, int n_in,
                              void* d_out, int out_size) {
    const float* x  = (const float*)d_in[0];
    const int*   tp = (const int*)  d_in[1];
    const float* Wq = (const float*)d_in[2];
    const float* Wk = (const float*)d_in[3];
    const float* Wv = (const float*)d_in[4];
    const float* Wo = (const float*)d_in[5];
    float* out = (float*)d_out;

    float *gq, *gk, *gv, *ga;
    __nv_bfloat16 *hx, *lx, *hw, *lw;
    cudaGetSymbolAddress((void**)&gq, g_Q);
    cudaGetSymbolAddress((void**)&gk, g_K);
    cudaGetSymbolAddress((void**)&gv, g_V);
    cudaGetSymbolAddress((void**)&ga, g_A);
    cudaGetSymbolAddress((void**)&hx, g_hiX);
    cudaGetSymbolAddress((void**)&lx, g_loX);
    cudaGetSymbolAddress((void**)&hw, g_hiW);
    cudaGetSymbolAddress((void**)&lw, g_loW);

    const int mma_smem = 2 * BUF_B;   // 81920 B
    cudaFuncSetAttribute(mma_gemm_kernel<0>,
                         cudaFuncAttributeMaxDynamicSharedMemorySize, mma_smem);
    cudaFuncSetAttribute(mma_gemm_kernel<1>,
                         cudaFuncAttributeMaxDynamicSharedMemorySize, mma_smem);
    cudaFuncSetAttribute(mma_gemm_kernel<2>,
                         cudaFuncAttributeMaxDynamicSharedMemorySize, mma_smem);

    rope_table_kernel<<<(SEQ * DHALF + 255) / 256, 256>>>(tp);

    const int NX = MROWS * DMODEL;
    const int NW = DMODEL * DMODEL;
    split_kernel<<<(NX + 255) / 256, 256>>>(x, hx, lx, NX);

    dim3 ggrid(DMODEL / 128, MROWS / 128);
    split_kernel<<<(NW + 255) / 256, 256>>>(Wq, hw, lw, NW);
    mma_gemm_kernel<1><<<ggrid, 256, mma_smem>>>(hx, lx, hw, lw, gq);
    split_kernel<<<(NW + 255) / 256, 256>>>(Wk, hw, lw, NW);
    mma_gemm_kernel<1><<<ggrid, 256, mma_smem>>>(hx, lx, hw, lw, gk);
    split_kernel<<<(NW + 255) / 256, 256>>>(Wv, hw, lw, NW);
    mma_gemm_kernel<2><<<ggrid, 256, mma_smem>>>(hx, lx, hw, lw, gv);

    const int fa_smem = (64 * 132 + 64 * 132 + 128 * 68 + 128 * 132) * sizeof(float);
    cudaFuncSetAttribute(flash_attn_kernel,
                         cudaFuncAttributeMaxDynamicSharedMemorySize, fa_smem);
    flash_attn_kernel<<<dim3(SEQ / 128, BATCH * NHEADS), 256, fa_smem>>>(ga);

    split_kernel<<<(NX + 255) / 256, 256>>>(ga, hx, lx, NX);
    split_kernel<<<(NW + 255) / 256, 256>>>(Wo, hw, lw, NW);
    mma_gemm_kernel<0><<<ggrid, 256, mma_smem>>>(hx, lx, hw, lw, out);
}